// round 12
// baseline (speedup 1.0000x reference)
#include <cuda_runtime.h>
#include <cuda_bf16.h>
#include <cstdint>

#define E_ 8
#define D_ 512
#define P_ 32
#define BMAX 8192
#define MTOK 64             // tokens per CTA; M = 128 rows (64 token + 64 anchor)
#define THREADS 256
#define FULLM 0xffffffffu

// padded bf16 row for B tile: 512 + 8 = 520 elems = 1040 B (ldmatrix conflict-free)
#define ROWB 1040

// ---- smem layout (bytes) ----
#define SM_B     0                       // 32 * 1040 = 33280; reused as cross[128][36] after MMA
#define SM_S2    33280                   // 128 floats
#define SM_P2    33792                   // 32 floats
#define SMEM_BYTES 33920
#define SM_CROSS 0
#define CSTRIDE  36                      // float4-aligned epilogue rows

// ---- persistent scratch (module globals; no runtime alloc) ----
__device__ __align__(16) __nv_bfloat16 g_tokBF[BMAX * E_ * D_];   // 64 MB
__device__ __align__(16) __nv_bfloat16 g_proBF[E_ * P_ * D_];
__device__ float g_s2[BMAX * E_];
__device__ float g_p2[E_ * P_];
__device__ int   g_zero = 0;

static __device__ __forceinline__ uint32_t smem_u32(const void* p) {
    return (uint32_t)__cvta_generic_to_shared(p);
}

#define LDSM_X4(r0, r1, r2, r3, addr) \
    asm volatile("ldmatrix.sync.aligned.m8n8.x4.shared.b16 {%0,%1,%2,%3}, [%4];" \
        : "=r"(r0), "=r"(r1), "=r"(r2), "=r"(r3) : "r"(addr))

static __device__ __forceinline__ void mma16816(float* d, const uint32_t* a,
                                                uint32_t b0, uint32_t b1) {
    asm volatile(
        "mma.sync.aligned.m16n8k16.row.col.f32.bf16.bf16.f32 "
        "{%0,%1,%2,%3}, {%4,%5,%6,%7}, {%8,%9}, {%0,%1,%2,%3};"
        : "+f"(d[0]), "+f"(d[1]), "+f"(d[2]), "+f"(d[3])
        : "r"(a[0]), "r"(a[1]), "r"(a[2]), "r"(a[3]), "r"(b0), "r"(b1));
}

static __device__ __forceinline__ uint32_t packbf(float x, float y) {
    __nv_bfloat162 h = __floats2bfloat162_rn(x, y);
    return *reinterpret_cast<uint32_t*>(&h);
}

static __device__ __forceinline__ float frcp(float x) {
    float y;
    asm("rcp.approx.f32 %0, %1;" : "=f"(y) : "f"(x));
    return y;
}

// ---------------- prepass: fp32 -> bf16 + row norms (pure streaming) ----------------
// one warp per 512-float row
__global__ __launch_bounds__(256)
void prep_tok(const float* __restrict__ src, int nrows) {
    const int row  = blockIdx.x * 8 + (threadIdx.x >> 5);
    const int lane = threadIdx.x & 31;
    if (row >= nrows) return;
    const float4* s4 = (const float4*)(src + (size_t)row * D_);
    float nrm = 0.f;
    #pragma unroll
    for (int j = 0; j < 4; ++j) {
        float4 v = s4[j * 32 + lane];
        nrm = fmaf(v.x, v.x, fmaf(v.y, v.y, fmaf(v.z, v.z, fmaf(v.w, v.w, nrm))));
        uint2 pk;
        pk.x = packbf(v.x, v.y);
        pk.y = packbf(v.z, v.w);
        *reinterpret_cast<uint2*>(g_tokBF + (size_t)row * D_ + j * 128 + lane * 4) = pk;
    }
    #pragma unroll
    for (int o = 16; o; o >>= 1) nrm += __shfl_xor_sync(FULLM, nrm, o);
    if (lane == 0) g_s2[row] = nrm;
}

__global__ __launch_bounds__(256)
void prep_pro(const float* __restrict__ src) {
    const int row  = blockIdx.x * 8 + (threadIdx.x >> 5);   // 0..255
    const int lane = threadIdx.x & 31;
    const float4* s4 = (const float4*)(src + (size_t)row * D_);
    float nrm = 0.f;
    #pragma unroll
    for (int j = 0; j < 4; ++j) {
        float4 v = s4[j * 32 + lane];
        nrm = fmaf(v.x, v.x, fmaf(v.y, v.y, fmaf(v.z, v.z, fmaf(v.w, v.w, nrm))));
        uint2 pk;
        pk.x = packbf(v.x, v.y);
        pk.y = packbf(v.z, v.w);
        *reinterpret_cast<uint2*>(g_proBF + (size_t)row * D_ + j * 128 + lane * 4) = pk;
    }
    #pragma unroll
    for (int o = 16; o; o >>= 1) nrm += __shfl_xor_sync(FULLM, nrm, o);
    if (lane == 0) g_p2[row] = nrm;
}

// ---------------- main kernel: bf16 HMMA + collapsed Sinkhorn ----------------
__global__ __launch_bounds__(THREADS, 4)
void otng_hmma(const int* __restrict__ fi_ptr, float* __restrict__ out, int B) {
    extern __shared__ char smem[];
    const int e    = blockIdx.x;
    const int fi   = *fi_ptr;
    const int b0   = blockIdx.y * MTOK;
    const int tid  = threadIdx.x;
    const int wid  = tid >> 5;
    const int lane = tid & 31;
    const int BE   = B * E_;

    if (e == fi) {                        // trivial expert
        if (tid < MTOK) {
            int b = b0 + tid;
            out[b * E_ + e]      = 1.0f;
            out[BE + b * E_ + e] = 0.0f;
        }
        return;
    }

    const uint32_t sbase = smem_u32(smem);
    float* s2s = (float*)(smem + SM_S2);
    float* p2s = (float*)(smem + SM_P2);

    // load norms
    if (tid < 128) {
        const int c = (tid < 64) ? e : fi;
        s2s[tid] = g_s2[(b0 + (tid & 63)) * E_ + c];
    }
    if (tid < P_) p2s[tid] = g_p2[e * P_ + tid];

    // ---- stage B: 32 bf16 prototypes, superblock k-permutation ----
    // superblock bb holds actual k in [32bb, 32bb+32); quad slot m owns kk=8m..8m+7.
    // frag0 (bytes bb*64+[0,32)):  pair(8m,8m+1)@m*4,  pair(8m+2,8m+3)@16+m*4
    // frag1 (bytes bb*64+[32,64)): pair(8m+4,8m+5)@m*4, pair(8m+6,8m+7)@16+m*4
    #pragma unroll 1
    for (int k = 0; k < 4; ++k) {
        const int p = wid + k * 8;                    // 0..31
        const __nv_bfloat16* src = g_proBF + ((size_t)e * P_ + p) * D_;
        #pragma unroll
        for (int j = 0; j < 2; ++j) {
            const int c8 = j * 32 + lane;             // owns kk = 8*c8 .. 8*c8+7
            uint4 u = *reinterpret_cast<const uint4*>(src + 8 * c8);
            const int bb = c8 >> 2;
            const int m  = c8 & 3;
            char* base = smem + SM_B + p * ROWB + bb * 64 + m * 4;
            *reinterpret_cast<uint32_t*>(base)      = u.x;
            *reinterpret_cast<uint32_t*>(base + 16) = u.y;
            *reinterpret_cast<uint32_t*>(base + 32) = u.z;
            *reinterpret_cast<uint32_t*>(base + 48) = u.w;
        }
    }
    __syncthreads();

    // ---- HMMA GEMM: A bf16 direct from global (L2-resident), no conversion ----
    float acc[16];
    #pragma unroll
    for (int i = 0; i < 16; ++i) acc[i] = 0.f;
    {
        const int gr  = lane >> 2;
        const int m   = lane & 3;
        const int r0  = wid * 16 + gr;                // r1 = r0 + 8, same region
        const int col = (r0 < 64) ? e : fi;
        const int bt0 = b0 + (r0 & 63);
        const __nv_bfloat16* pA0 = g_tokBF + ((size_t)bt0 * E_ + col) * D_ + 8 * m;
        const __nv_bfloat16* pA1 = g_tokBF + ((size_t)(bt0 + 8) * E_ + col) * D_ + 8 * m;

        const int bn  = (lane & 7) + ((lane >> 4) << 3);
        const int bk  = ((lane >> 3) & 1) * 8;
        const uint32_t bAddr0 = sbase + SM_B + (uint32_t)bn * ROWB + (uint32_t)(bk * 2);
        const uint32_t bAddr1 = bAddr0 + 16u * ROWB;

        #pragma unroll 4
        for (int sb = 0; sb < 16; ++sb) {             // 2 MMA k-steps per superblock
            uint4 u0 = *reinterpret_cast<const uint4*>(pA0 + sb * 32);
            uint4 u1 = *reinterpret_cast<const uint4*>(pA1 + sb * 32);
            uint32_t a0[4], a1[4];
            a0[0] = u0.x; a0[1] = u1.x; a0[2] = u0.y; a0[3] = u1.y;
            a1[0] = u0.z; a1[1] = u1.z; a1[2] = u0.w; a1[3] = u1.w;

            uint32_t p0, p1, p2, p3, q0, q1, q2, q3;
            LDSM_X4(p0, p1, p2, p3, bAddr0 + sb * 64);
            LDSM_X4(q0, q1, q2, q3, bAddr1 + sb * 64);
            mma16816(acc + 0,  a0, p0, p1);
            mma16816(acc + 4,  a0, p2, p3);
            mma16816(acc + 8,  a0, q0, q1);
            mma16816(acc + 12, a0, q2, q3);

            LDSM_X4(p0, p1, p2, p3, bAddr0 + sb * 64 + 32);
            LDSM_X4(q0, q1, q2, q3, bAddr1 + sb * 64 + 32);
            mma16816(acc + 0,  a1, p0, p1);
            mma16816(acc + 4,  a1, p2, p3);
            mma16816(acc + 8,  a1, q0, q1);
            mma16816(acc + 12, a1, q2, q3);
        }
    }
    __syncthreads();   // all ldsm reads of B done -> safe to overwrite with cross

    // ---- scatter accumulators to cross[128][36] (reuses B region) ----
    float* crossS = (float*)(smem + SM_CROSS);
    {
        const int r0 = wid * 16 + (lane >> 2);
        const int c0 = 2 * (lane & 3);
        #pragma unroll
        for (int nt = 0; nt < 4; ++nt) {
            const int col = nt * 8 + c0;
            *(float2*)(crossS + (size_t)r0 * CSTRIDE + col)       = make_float2(acc[nt*4+0], acc[nt*4+1]);
            *(float2*)(crossS + (size_t)(r0 + 8) * CSTRIDE + col) = make_float2(acc[nt*4+2], acc[nt*4+3]);
        }
    }
    __syncthreads();

    // ---- epilogue: quad = one token, lane holds 8 prototypes in registers ----
    // Sinkhorn fixed point: S(r) = sum_p 1/(1 + cp_p r) = 16; Newton from r=0 is
    // monotone-increasing & convergent (S convex decreasing, S(0)=32).
    {
        const int T  = tid >> 2;                      // token 0..63
        const int pl = (tid & 3) * 8;                 // this lane's 8 prototypes
        const float s2t = s2s[T];
        const float s2a = s2s[64 + T];

        float4 ct0 = *(const float4*)(crossS + (size_t)T * CSTRIDE + pl);
        float4 ct1 = *(const float4*)(crossS + (size_t)T * CSTRIDE + pl + 4);
        float4 ca0 = *(const float4*)(crossS + (size_t)(64 + T) * CSTRIDE + pl);
        float4 ca1 = *(const float4*)(crossS + (size_t)(64 + T) * CSTRIDE + pl + 4);
        float4 pv0 = *(const float4*)(p2s + pl);
        float4 pv1 = *(const float4*)(p2s + pl + 4);

        float ctv[8] = {ct0.x, ct0.y, ct0.z, ct0.w, ct1.x, ct1.y, ct1.z, ct1.w};
        float cav[8] = {ca0.x, ca0.y, ca0.z, ca0.w, ca1.x, ca1.y, ca1.z, ca1.w};
        float pvv[8] = {pv0.x, pv0.y, pv0.z, pv0.w, pv1.x, pv1.y, pv1.z, pv1.w};

        float cp[8], d01[8], sc1 = 0.f;
        #pragma unroll
        for (int j = 0; j < 8; ++j) {
            float c0 = fmaxf(fmaf(-2.f, ctv[j], s2t) + pvv[j], 0.f);
            float c1 = fmaxf(fmaf(-2.f, cav[j], s2a) + pvv[j], 0.f);
            d01[j] = c0 - c1;
            sc1   += c1;
            cp[j]  = __expf(20.f * (c0 - c1));        // kb/ka
        }

        float r = 0.f;
        #pragma unroll 1
        for (int it = 0; it < 6; ++it) {
            float f = 0.f, g = 0.f;
            #pragma unroll
            for (int j = 0; j < 8; ++j) {
                float u = frcp(fmaf(cp[j], r, 1.f));
                f += u;
                g = fmaf(cp[j], u * u, g);
            }
            f += __shfl_xor_sync(FULLM, f, 1);
            f += __shfl_xor_sync(FULLM, f, 2);
            g += __shfl_xor_sync(FULLM, g, 1);
            g += __shfl_xor_sync(FULLM, g, 2);
            r = fmaf(f - 16.f, frcp(g), r);
        }

        float ot = sc1;
        #pragma unroll
        for (int j = 0; j < 8; ++j) {
            float w = frcp(fmaf(cp[j], r, 1.f));
            ot = fmaf(w, d01[j], ot);                 // sum_p [w*d01 + c1]
        }
        ot += __shfl_xor_sync(FULLM, ot, 1);
        ot += __shfl_xor_sync(FULLM, ot, 2);

        if ((tid & 3) == 0) {
            const int b = b0 + T;
            float o_  = ot * (1.f / 32.f);
            float val = frcp(1.f + __expf(6.f * (o_ - 0.25f)));
            out[b * E_ + e]      = val;
            out[BE + b * E_ + e] = o_;
        }
    }
}

// ---------------- launch ----------------
extern "C" void kernel_launch(void* const* d_in, const int* in_sizes, int n_in,
                              void* d_out, int out_size) {
    const float* tokens = (const float*)d_in[0];
    const float* protos = (const float*)d_in[1];
    const int* fi;
    if (n_in >= 3) {
        fi = (const int*)d_in[2];
    } else {
        void* zp = nullptr;
        cudaGetSymbolAddress(&zp, g_zero);
        fi = (const int*)zp;
    }
    float* out = (float*)d_out;
    const int B = in_sizes[0] / (E_ * D_);
    const int nrows = B * E_;

    prep_tok<<<(nrows + 7) / 8, 256>>>(tokens, nrows);
    prep_pro<<<E_ * P_ / 8, 256>>>(protos);

    cudaFuncSetAttribute(otng_hmma,
                         cudaFuncAttributeMaxDynamicSharedMemorySize, SMEM_BYTES);
    dim3 grid(E_, B / MTOK);
    otng_hmma<<<grid, THREADS, SMEM_BYTES>>>(fi, out, B);
}

// round 14
// speedup vs baseline: 1.0708x; 1.0708x over previous
#include <cuda_runtime.h>
#include <cuda_bf16.h>
#include <cstdint>

#define E_ 8
#define D_ 512
#define P_ 32
#define BMAX 8192
#define MTOK 64
#define THREADS 256
#define FULLM 0xffffffffu
#define GOFF 16                          // main group offset (software pipeline)

#define ROWB 1040

// ---- smem layout (bytes) ----
#define SM_B     0                       // 32*1040 = 33280; reused as cross[128][36]
#define SM_S2    33280                   // 128 floats
#define SM_P2    33792                   // 32 floats
#define SMEM_BYTES 33920
#define SM_CROSS 0
#define CSTRIDE  36

// ---- persistent scratch ----
__device__ __align__(16) __nv_bfloat16 g_tokBF[(size_t)BMAX * E_ * D_];
__device__ float g_s2[E_ * BMAX];        // [col][b] — lines never span flag domains
__device__ int   g_flags[(BMAX / MTOK) * E_];
__device__ int   g_zero = 0;

static __device__ __forceinline__ uint32_t smem_u32(const void* p) {
    return (uint32_t)__cvta_generic_to_shared(p);
}

#define LDSM_X4(r0, r1, r2, r3, addr) \
    asm volatile("ldmatrix.sync.aligned.m8n8.x4.shared.b16 {%0,%1,%2,%3}, [%4];" \
        : "=r"(r0), "=r"(r1), "=r"(r2), "=r"(r3) : "r"(addr))

static __device__ __forceinline__ void mma16816(float* d, const uint32_t* a,
                                                uint32_t b0, uint32_t b1) {
    asm volatile(
        "mma.sync.aligned.m16n8k16.row.col.f32.bf16.bf16.f32 "
        "{%0,%1,%2,%3}, {%4,%5,%6,%7}, {%8,%9}, {%0,%1,%2,%3};"
        : "+f"(d[0]), "+f"(d[1]), "+f"(d[2]), "+f"(d[3])
        : "r"(a[0]), "r"(a[1]), "r"(a[2]), "r"(a[3]), "r"(b0), "r"(b1));
}

static __device__ __forceinline__ uint32_t packbf(float x, float y) {
    __nv_bfloat162 h = __floats2bfloat162_rn(x, y);
    return *reinterpret_cast<uint32_t*>(&h);
}

static __device__ __forceinline__ float frcp(float x) {
    float y;
    asm("rcp.approx.f32 %0, %1;" : "=f"(y) : "f"(x));
    return y;
}

static __device__ __forceinline__ int ld_acquire(const int* p) {
    int v;
    asm volatile("ld.acquire.gpu.b32 %0, [%1];" : "=r"(v) : "l"(p) : "memory");
    return v;
}

// ---------------- flag reset (runs first, every call) ----------------
__global__ void zero_flags(int n) {
    int i = blockIdx.x * blockDim.x + threadIdx.x;
    if (i < n) g_flags[i] = 0;
}

// ---------------- fused kernel: pipelined prep + main ----------------
// gid = blockIdx.x >> 4, slot = blockIdx.x & 15, G = B/64 groups.
//   slot 0-7 , gid < G        : prep token block gid, column `slot`
//   slot 8-15, gid in [GOFF,G+GOFF): main for block bb = gid-GOFF, expert slot-8
__global__ __launch_bounds__(THREADS, 4)
void otng_fused(const float* __restrict__ tokens,
                const float* __restrict__ protos,
                const int* __restrict__ fi_ptr,
                float* __restrict__ out, int B) {
    extern __shared__ char smem[];
    const int G    = B / MTOK;
    const int gid  = blockIdx.x >> 4;
    const int slot = blockIdx.x & 15;
    const int tid  = threadIdx.x;
    const int wid  = tid >> 5;
    const int lane = tid & 31;

    if (slot < 8) {
        if (gid >= G) return;
        // ======== PREP: convert 64 rows of column `slot` for block gid ========
        const int b0  = gid * MTOK;
        const int col = slot;
        #pragma unroll 2
        for (int rr = 0; rr < 8; ++rr) {
            const int b = b0 + wid * 8 + rr;
            const float4* s4 = (const float4*)(tokens + ((size_t)b * E_ + col) * D_);
            __nv_bfloat16* dst = g_tokBF + ((size_t)b * E_ + col) * D_;
            float nrm = 0.f;
            #pragma unroll
            for (int j = 0; j < 4; ++j) {
                float4 v = s4[j * 32 + lane];
                nrm = fmaf(v.x, v.x, fmaf(v.y, v.y, fmaf(v.z, v.z, fmaf(v.w, v.w, nrm))));
                uint2 pk;
                pk.x = packbf(v.x, v.y);
                pk.y = packbf(v.z, v.w);
                *reinterpret_cast<uint2*>(dst + j * 128 + lane * 4) = pk;
            }
            #pragma unroll
            for (int o = 16; o; o >>= 1) nrm += __shfl_xor_sync(FULLM, nrm, o);
            if (lane == 0) g_s2[col * BMAX + b] = nrm;   // [col][b] layout
        }
        __threadfence();
        __syncthreads();
        if (tid == 0) atomicExch(&g_flags[gid * 8 + col], 1);
        return;
    }

    // ======== MAIN: expert e on token block bb = gid - GOFF ========
    const int bb = gid - GOFF;
    if (bb < 0 || bb >= G) return;
    const int b0 = bb * MTOK;
    const int e  = slot - 8;
    const int fi = *fi_ptr;
    const int BE = B * E_;

    if (e == fi) {
        if (tid < MTOK) {
            int b = b0 + tid;
            out[b * E_ + e]      = 1.0f;
            out[BE + b * E_ + e] = 0.0f;
        }
        return;
    }

    const uint32_t sbase = smem_u32(smem);
    float* s2s = (float*)(smem + SM_S2);
    float* p2s = (float*)(smem + SM_P2);

    // ---- stage B from fp32 protos: superblock k-permutation + p2 norms ----
    #pragma unroll 1
    for (int k = 0; k < 4; ++k) {
        const int p = wid + k * 8;
        const float* src = protos + ((size_t)e * P_ + p) * D_;
        float nrm = 0.f;
        #pragma unroll
        for (int j = 0; j < 2; ++j) {
            const int c8 = j * 32 + lane;            // owns kk = 8*c8..8*c8+7
            float4 va = *(const float4*)(src + 8 * c8);
            float4 vb = *(const float4*)(src + 8 * c8 + 4);
            nrm = fmaf(va.x, va.x, fmaf(va.y, va.y, fmaf(va.z, va.z, fmaf(va.w, va.w, nrm))));
            nrm = fmaf(vb.x, vb.x, fmaf(vb.y, vb.y, fmaf(vb.z, vb.z, fmaf(vb.w, vb.w, nrm))));
            const int bbk = c8 >> 2;
            const int m   = c8 & 3;
            char* base = smem + SM_B + p * ROWB + bbk * 64 + m * 4;
            *reinterpret_cast<uint32_t*>(base)      = packbf(va.x, va.y);
            *reinterpret_cast<uint32_t*>(base + 16) = packbf(va.z, va.w);
            *reinterpret_cast<uint32_t*>(base + 32) = packbf(vb.x, vb.y);
            *reinterpret_cast<uint32_t*>(base + 48) = packbf(vb.z, vb.w);
        }
        #pragma unroll
        for (int o = 16; o; o >>= 1) nrm += __shfl_xor_sync(FULLM, nrm, o);
        if (lane == 0) p2s[p] = nrm;
    }

    // ---- wait (acquire) for this block's token + anchor columns ----
    if (tid == 0) {
        while (ld_acquire(&g_flags[bb * 8 + e]) == 0)  __nanosleep(64);
        while (ld_acquire(&g_flags[bb * 8 + fi]) == 0) __nanosleep(64);
    }
    __syncthreads();

    // norms (from prep; [col][b] layout — lines exclusively flag-owned)
    if (tid < 128) {
        const int c = (tid < 64) ? e : fi;
        s2s[tid] = g_s2[c * BMAX + b0 + (tid & 63)];
    }
    __syncthreads();

    // ---- HMMA GEMM: bf16 A direct from g_tokBF ----
    float acc[16];
    #pragma unroll
    for (int i = 0; i < 16; ++i) acc[i] = 0.f;
    {
        const int gr  = lane >> 2;
        const int m   = lane & 3;
        const int r0  = wid * 16 + gr;
        const int col = (r0 < 64) ? e : fi;
        const int bt0 = b0 + (r0 & 63);
        const __nv_bfloat16* pA0 = g_tokBF + ((size_t)bt0 * E_ + col) * D_ + 8 * m;
        const __nv_bfloat16* pA1 = g_tokBF + ((size_t)(bt0 + 8) * E_ + col) * D_ + 8 * m;

        const int bn  = (lane & 7) + ((lane >> 4) << 3);
        const int bk  = ((lane >> 3) & 1) * 8;
        const uint32_t bAddr0 = sbase + SM_B + (uint32_t)bn * ROWB + (uint32_t)(bk * 2);
        const uint32_t bAddr1 = bAddr0 + 16u * ROWB;

        #pragma unroll 4
        for (int sb = 0; sb < 16; ++sb) {
            uint4 u0 = *reinterpret_cast<const uint4*>(pA0 + sb * 32);
            uint4 u1 = *reinterpret_cast<const uint4*>(pA1 + sb * 32);
            uint32_t a0[4], a1[4];
            a0[0] = u0.x; a0[1] = u1.x; a0[2] = u0.y; a0[3] = u1.y;
            a1[0] = u0.z; a1[1] = u1.z; a1[2] = u0.w; a1[3] = u1.w;

            uint32_t p0, p1, p2, p3, q0, q1, q2, q3;
            LDSM_X4(p0, p1, p2, p3, bAddr0 + sb * 64);
            LDSM_X4(q0, q1, q2, q3, bAddr1 + sb * 64);
            mma16816(acc + 0,  a0, p0, p1);
            mma16816(acc + 4,  a0, p2, p3);
            mma16816(acc + 8,  a0, q0, q1);
            mma16816(acc + 12, a0, q2, q3);

            LDSM_X4(p0, p1, p2, p3, bAddr0 + sb * 64 + 32);
            LDSM_X4(q0, q1, q2, q3, bAddr1 + sb * 64 + 32);
            mma16816(acc + 0,  a1, p0, p1);
            mma16816(acc + 4,  a1, p2, p3);
            mma16816(acc + 8,  a1, q0, q1);
            mma16816(acc + 12, a1, q2, q3);
        }
    }
    __syncthreads();

    // ---- scatter accumulators to cross[128][36] (reuses B region) ----
    float* crossS = (float*)(smem + SM_CROSS);
    {
        const int r0 = wid * 16 + (lane >> 2);
        const int c0 = 2 * (lane & 3);
        #pragma unroll
        for (int nt = 0; nt < 4; ++nt) {
            const int col = nt * 8 + c0;
            *(float2*)(crossS + (size_t)r0 * CSTRIDE + col)       = make_float2(acc[nt*4+0], acc[nt*4+1]);
            *(float2*)(crossS + (size_t)(r0 + 8) * CSTRIDE + col) = make_float2(acc[nt*4+2], acc[nt*4+3]);
        }
    }
    __syncthreads();

    // ---- epilogue: quad = one token; Newton on S(r)=sum 1/(1+cp r)=16 ----
    {
        const int T  = tid >> 2;
        const int pl = (tid & 3) * 8;
        const float s2t = s2s[T];
        const float s2a = s2s[64 + T];

        float4 ct0 = *(const float4*)(crossS + (size_t)T * CSTRIDE + pl);
        float4 ct1 = *(const float4*)(crossS + (size_t)T * CSTRIDE + pl + 4);
        float4 ca0 = *(const float4*)(crossS + (size_t)(64 + T) * CSTRIDE + pl);
        float4 ca1 = *(const float4*)(crossS + (size_t)(64 + T) * CSTRIDE + pl + 4);
        float4 pv0 = *(const float4*)(p2s + pl);
        float4 pv1 = *(const float4*)(p2s + pl + 4);

        float ctv[8] = {ct0.x, ct0.y, ct0.z, ct0.w, ct1.x, ct1.y, ct1.z, ct1.w};
        float cav[8] = {ca0.x, ca0.y, ca0.z, ca0.w, ca1.x, ca1.y, ca1.z, ca1.w};
        float pvv[8] = {pv0.x, pv0.y, pv0.z, pv0.w, pv1.x, pv1.y, pv1.z, pv1.w};

        float cp[8], d01[8], sc1 = 0.f;
        #pragma unroll
        for (int j = 0; j < 8; ++j) {
            float c0 = fmaxf(fmaf(-2.f, ctv[j], s2t) + pvv[j], 0.f);
            float c1 = fmaxf(fmaf(-2.f, cav[j], s2a) + pvv[j], 0.f);
            d01[j] = c0 - c1;
            sc1   += c1;
            cp[j]  = __expf(20.f * (c0 - c1));
        }

        float r = 0.f;
        #pragma unroll 1
        for (int it = 0; it < 6; ++it) {
            float f = 0.f, g = 0.f;
            #pragma unroll
            for (int j = 0; j < 8; ++j) {
                float u = frcp(fmaf(cp[j], r, 1.f));
                f += u;
                g = fmaf(cp[j], u * u, g);
            }
            f += __shfl_xor_sync(FULLM, f, 1);
            f += __shfl_xor_sync(FULLM, f, 2);
            g += __shfl_xor_sync(FULLM, g, 1);
            g += __shfl_xor_sync(FULLM, g, 2);
            r = fmaf(f - 16.f, frcp(g), r);
        }

        float ot = sc1;
        #pragma unroll
        for (int j = 0; j < 8; ++j) {
            float w = frcp(fmaf(cp[j], r, 1.f));
            ot = fmaf(w, d01[j], ot);
        }
        ot += __shfl_xor_sync(FULLM, ot, 1);
        ot += __shfl_xor_sync(FULLM, ot, 2);

        if ((tid & 3) == 0) {
            const int b = b0 + T;
            float o_  = ot * (1.f / 32.f);
            float val = frcp(1.f + __expf(6.f * (o_ - 0.25f)));
            out[b * E_ + e]      = val;
            out[BE + b * E_ + e] = o_;
        }
    }
}

// ---------------- launch ----------------
extern "C" void kernel_launch(void* const* d_in, const int* in_sizes, int n_in,
                              void* d_out, int out_size) {
    const float* tokens = (const float*)d_in[0];
    const float* protos = (const float*)d_in[1];
    const int* fi;
    if (n_in >= 3) {
        fi = (const int*)d_in[2];
    } else {
        void* zp = nullptr;
        cudaGetSymbolAddress(&zp, g_zero);
        fi = (const int*)zp;
    }
    float* out = (float*)d_out;
    const int B = in_sizes[0] / (E_ * D_);
    const int G = B / MTOK;
    const int nflags = G * E_;

    zero_flags<<<(nflags + 255) / 256, 256>>>(nflags);

    cudaFuncSetAttribute(otng_fused,
                         cudaFuncAttributeMaxDynamicSharedMemorySize, SMEM_BYTES);
    otng_fused<<<(G + GOFF) * 16, THREADS, SMEM_BYTES>>>(tokens, protos, fi, out, B);
}